// round 13
// baseline (speedup 1.0000x reference)
#include <cuda_runtime.h>
#include <cuda_bf16.h>
#include <cstdint>

// CRF loss: out[b] = logZ(b) - gold_score(b).  B=2048, L=512, T=32.
// Forward/backward split: logZ = log sum_i aF_m[i] * bB_m[i], m = ceil(len/2).
// Block bid<2048: forward alpha over rows [0,m).  bid>=2048: backward beta over
// rows [m,len).  32-lane scaled-prob matvec chain (~len/2 steps), renorm every
// 2nd step (fp32-safe: growth < e^30).  The SECOND half to finish (atomic
// ticket) fuses the combine: dot(aF,bB) + scales + gold -> out[b].

#define CRF_B 2048
#define CRF_L 512
#define CRF_T 32
#define CHUNK 8

__device__ float  g_aF[CRF_B * CRF_T];
__device__ float  g_bB[CRF_B * CRF_T];
__device__ float2 g_sF[CRF_B];        // {Ml2_fwd, gold_fwd}
__device__ float2 g_sB[CRF_B];        // {Ml2_bwd, gold_bwd}
__device__ int    g_ticket[CRF_B];    // zero-init; restored to 0 each launch

__device__ __forceinline__ unsigned smem_u32(const void* p) {
    return (unsigned)__cvta_generic_to_shared(p);
}

__global__ __launch_bounds__(32)
void crf_halves_kernel(const float* __restrict__ emit,      // (B, L, T)
                       const float* __restrict__ trans,     // (T, T)
                       const int*   __restrict__ tags,      // (B, L)
                       const int*   __restrict__ lengths,   // (B,)
                       float*       __restrict__ out)       // (B,)
{
    const unsigned FULL = 0xffffffffu;
    __shared__ __align__(16) float ebuf[2][CHUNK * CRF_T];
    __shared__ __align__(16) float pbuf[2][CRF_T];
    __shared__ __align__(16) int   tbuf[CRF_L];

    const int  lane = threadIdx.x;
    const bool bwd  = blockIdx.x >= CRF_B;
    const int  b    = bwd ? (blockIdx.x - CRF_B) : blockIdx.x;
    const int  len  = lengths[b];
    const int  m    = (len + 1) >> 1;       // fwd rows [0,m), bwd rows [m,len)

    {   // tags for this batch
        const int4* tg4 = (const int4*)(tags + (size_t)b * CRF_L);
        int4* tb4 = (int4*)tbuf;
#pragma unroll
        for (int i = 0; i < 4; i++)
            tb4[lane + 32 * i] = __ldg(&tg4[lane + 32 * i]);
    }

    // exp(transition), 16 f32x2 pairs per lane.
    // fwd: pairs over i of column `lane`.  bwd: pairs over j of row `lane`.
    unsigned long long Mp[16];
#pragma unroll
    for (int q = 0; q < 16; q++) {
        float m0, m1;
        if (!bwd) {
            m0 = __expf(__ldg(&trans[(2 * q + 0) * CRF_T + lane]));
            m1 = __expf(__ldg(&trans[(2 * q + 1) * CRF_T + lane]));
        } else {
            m0 = __expf(__ldg(&trans[lane * CRF_T + 2 * q + 0]));
            m1 = __expf(__ldg(&trans[lane * CRF_T + 2 * q + 1]));
        }
        asm("mov.b64 %0, {%1, %2};" : "=l"(Mp[q]) : "f"(m0), "f"(m1));
    }

    const float* erow = emit + (size_t)b * CRF_L * CRF_T;
    const unsigned pb0 = smem_u32(&pbuf[0][0]);
    const unsigned pb1 = smem_u32(&pbuf[1][0]);

    float Ml2 = 0.f;
    float gs  = 0.f;

    auto stage = [&](int c, bool ok) {
        if (ok) {
            const char* src = (const char*)(erow + c * (CHUNK * CRF_T));
            unsigned dst = smem_u32(&ebuf[c & 1][0]);
            asm volatile("cp.async.cg.shared.global [%0], [%1], 16;\n"
                         :: "r"(dst + lane * 16), "l"(src + lane * 16));
            asm volatile("cp.async.cg.shared.global [%0], [%1], 16;\n"
                         :: "r"(dst + 512 + lane * 16), "l"(src + 512 + lane * 16));
        }
        asm volatile("cp.async.commit_group;\n");
    };

    // matvec over the 32-vector published at smem[pin]; g gets element 0.
    auto matvec = [&](unsigned pin, float& g) -> float {
        unsigned long long A0 = 0ull, A1 = 0ull, A2 = 0ull, A3 = 0ull, x, y;
        asm volatile("ld.shared.v2.u64 {%0, %1}, [%2];" : "=l"(x), "=l"(y) : "r"(pin));
        { float hi; asm("mov.b64 {%0, %1}, %2;" : "=f"(g), "=f"(hi) : "l"(x)); }
        asm("fma.rn.f32x2 %0, %1, %2, %0;" : "+l"(A0) : "l"(x), "l"(Mp[0]));
        asm("fma.rn.f32x2 %0, %1, %2, %0;" : "+l"(A1) : "l"(y), "l"(Mp[1]));
#pragma unroll
        for (int q = 1; q < 8; q++) {
            asm volatile("ld.shared.v2.u64 {%0, %1}, [%2];"
                         : "=l"(x), "=l"(y) : "r"(pin + q * 16));
            if (q & 1) {
                asm("fma.rn.f32x2 %0, %1, %2, %0;" : "+l"(A2) : "l"(x), "l"(Mp[2 * q + 0]));
                asm("fma.rn.f32x2 %0, %1, %2, %0;" : "+l"(A3) : "l"(y), "l"(Mp[2 * q + 1]));
            } else {
                asm("fma.rn.f32x2 %0, %1, %2, %0;" : "+l"(A0) : "l"(x), "l"(Mp[2 * q + 0]));
                asm("fma.rn.f32x2 %0, %1, %2, %0;" : "+l"(A1) : "l"(y), "l"(Mp[2 * q + 1]));
            }
        }
        asm("add.rn.f32x2 %0, %0, %1;" : "+l"(A0) : "l"(A1));
        asm("add.rn.f32x2 %0, %0, %1;" : "+l"(A2) : "l"(A3));
        asm("add.rn.f32x2 %0, %0, %1;" : "+l"(A0) : "l"(A2));
        float s0, s1;
        asm("mov.b64 {%0, %1}, %2;" : "=f"(s0), "=f"(s1) : "l"(A0));
        return s0 + s1;
    };

    __syncthreads();   // tbuf visible

    float v = 0.f;     // this lane's final partial vector value (aF or bB)

    if (!bwd) {
        // ---------------- FORWARD: rows [0, m) ----------------
        const int nch = (m + CHUNK - 1) / CHUNK;
        stage(0, 0 < nch);
        stage(1, 1 < nch);
        float a = 0.f;

        for (int c = 0; c < nch; c++) {
            asm volatile("cp.async.wait_group 1;\n" ::: "memory");
            __syncthreads();
            const float* E = &ebuf[c & 1][0];

            float w[CHUNK];
#pragma unroll
            for (int k = 0; k < CHUNK; k++) w[k] = __expf(E[k * CRF_T + lane]);

            {   // gold partials, rows [0, m)
                const int r = c * CHUNK + lane;
                if (lane < CHUNK && r < m) {
                    const int tg = tbuf[r];
                    gs += E[lane * CRF_T + tg];
                    if (r >= 1) gs += __ldg(&trans[tbuf[r - 1] * CRF_T + tg]);
                }
            }
            stage(c + 2, c + 2 < nch);

#pragma unroll
            for (int k = 0; k < CHUNK; k++) {
                const int row = c * CHUNK + k;
                if (row == 0) {
                    a = w[0];
                    pbuf[0][lane] = a;
                    __syncthreads();
                } else if (row < m) {
                    const unsigned pin  = ((row - 1) & 1) ? pb1 : pb0;
                    const unsigned pout = (row & 1)       ? pb1 : pb0;
                    float g;
                    float s = matvec(pin, g);
                    if ((k & 1) == 0) {      // renorm every 2nd step
                        float rg; asm("rcp.approx.f32 %0, %1;" : "=f"(rg) : "f"(g));
                        Ml2 += __log2f(g);
                        a = s * (w[k] * rg);
                    } else {
                        a = s * w[k];
                    }
                    asm volatile("st.shared.f32 [%0], %1;" :: "r"(pout + lane * 4), "f"(a));
                    __syncthreads();
                }
            }
        }
        // final renorm by lane-0 value (bounds cross-half products)
        float a0 = __shfl_sync(FULL, a, 0);
        { float rg; asm("rcp.approx.f32 %0, %1;" : "=f"(rg) : "f"(a0)); a *= rg; }
        Ml2 += __log2f(a0);
        v = a;
    } else {
        // ---------------- BACKWARD: rows [m, len), high to low ----------------
        const int cL = (len - 1) >> 3;
        const int c0 = m >> 3;
        stage(cL, true);
        stage(cL - 1, cL - 1 >= c0);
        float bta = 1.f;                     // beta_{len-1} = 1

        for (int c = cL; c >= c0; c--) {
            asm volatile("cp.async.wait_group 1;\n" ::: "memory");
            __syncthreads();
            const float* E = &ebuf[c & 1][0];

            float w[CHUNK];
#pragma unroll
            for (int k = 0; k < CHUNK; k++) w[k] = __expf(E[k * CRF_T + lane]);

            {   // gold partials, rows [m, len); r>=m>=1 so transition always
                const int r = c * CHUNK + lane;
                if (lane < CHUNK && r >= m && r < len) {
                    const int tg = tbuf[r];
                    gs += E[lane * CRF_T + tg];
                    gs += __ldg(&trans[tbuf[r - 1] * CRF_T + tg]);
                }
            }
            stage(c - 2, c - 2 >= c0);

#pragma unroll
            for (int k = CHUNK - 1; k >= 0; k--) {
                const int row = c * CHUNK + k;
                if (row >= m && row < len) {
                    const float q = w[k] * bta;
                    const unsigned pout = (row & 1) ? pb1 : pb0;
                    asm volatile("st.shared.f32 [%0], %1;" :: "r"(pout + lane * 4), "f"(q));
                    __syncthreads();
                    float g;
                    float s = matvec(pout, g);
                    if ((k & 1) == 0) {      // renorm every 2nd step
                        float rg; asm("rcp.approx.f32 %0, %1;" : "=f"(rg) : "f"(g));
                        Ml2 += __log2f(g);
                        bta = s * rg;
                    } else {
                        bta = s;
                    }
                }
            }
        }
        // final renorm by lane-0 value
        float b0 = __shfl_sync(FULL, bta, 0);
        { float rg; asm("rcp.approx.f32 %0, %1;" : "=f"(rg) : "f"(b0)); bta *= rg; }
        Ml2 += __log2f(b0);
        v = bta;
    }

    // Reduce gold partials (all lanes get the value).
#pragma unroll
    for (int off = 16; off; off >>= 1)
        gs += __shfl_xor_sync(FULL, gs, off);

    // Publish partials, then ticket: the SECOND arriver fuses the combine.
    if (!bwd) {
        __stcg(&g_aF[b * CRF_T + lane], v);
        if (lane == 0) __stcg(&g_sF[b], make_float2(Ml2, gs));
    } else {
        __stcg(&g_bB[b * CRF_T + lane], v);
        if (lane == 0) __stcg(&g_sB[b], make_float2(Ml2, gs));
    }
    __threadfence();

    int old = 0;
    if (lane == 0) old = atomicAdd(&g_ticket[b], 1);
    old = __shfl_sync(FULL, old, 0);

    if (old == 1) {
        __threadfence();
        float  pv = bwd ? __ldcg(&g_aF[b * CRF_T + lane])
                        : __ldcg(&g_bB[b * CRF_T + lane]);
        float2 sp = bwd ? __ldcg(&g_sF[b]) : __ldcg(&g_sB[b]);

        float prod = v * pv;
#pragma unroll
        for (int off = 16; off; off >>= 1)
            prod += __shfl_xor_sync(FULL, prod, off);

        const float logz = (Ml2 + sp.x) * 0.6931471805599453f + __logf(prod);
        if (lane == 0) {
            out[b] = logz - (gs + sp.y);
            g_ticket[b] = 0;               // restore for next graph replay
        }
    }
}

extern "C" void kernel_launch(void* const* d_in, const int* in_sizes, int n_in,
                              void* d_out, int out_size)
{
    const float* emit    = (const float*)d_in[0];
    const float* trans   = (const float*)d_in[1];
    const int*   tags    = (const int*)d_in[2];
    const int*   lengths = (const int*)d_in[3];
    float*       out     = (float*)d_out;

    (void)in_sizes; (void)n_in; (void)out_size;

    crf_halves_kernel<<<2 * CRF_B, 32>>>(emit, trans, tags, lengths, out);
}

// round 14
// speedup vs baseline: 1.5958x; 1.5958x over previous
#include <cuda_runtime.h>
#include <cuda_bf16.h>
#include <cstdint>

// CRF loss: out[b] = logZ(b) - gold_score(b).  B=2048, L=512, T=32.
// Forward/backward split: logZ = log sum_i aF_m[i] * bB_m[i], m = ceil(len/2).
// Block bid<2048: forward alpha over rows [0,m).  bid>=2048: backward beta over
// rows [m,len).  32-lane scaled-prob matvec chain (~len/2 steps), renorm every
// 2nd step (fp32-safe; validated rel_err ~1.6e-7).  Separate tiny combine
// kernel (NO device-scope fences in the halves kernel: a gpu-scope fence
// emits CCTL.IVALL on Blackwell and thrashes L1 for co-resident blocks —
// measured +45us in R13).

#define CRF_B 2048
#define CRF_L 512
#define CRF_T 32
#define CHUNK 8

__device__ float  g_aF[CRF_B * CRF_T];
__device__ float  g_bB[CRF_B * CRF_T];
__device__ float2 g_sF[CRF_B];   // {Ml2_fwd, gold_fwd}
__device__ float2 g_sB[CRF_B];   // {Ml2_bwd, gold_bwd}

__device__ __forceinline__ unsigned smem_u32(const void* p) {
    return (unsigned)__cvta_generic_to_shared(p);
}

__global__ __launch_bounds__(32)
void crf_halves_kernel(const float* __restrict__ emit,      // (B, L, T)
                       const float* __restrict__ trans,     // (T, T)
                       const int*   __restrict__ tags,      // (B, L)
                       const int*   __restrict__ lengths)   // (B,)
{
    const unsigned FULL = 0xffffffffu;
    __shared__ __align__(16) float ebuf[2][CHUNK * CRF_T];
    __shared__ __align__(16) float pbuf[2][CRF_T];
    __shared__ __align__(16) int   tbuf[CRF_L];

    const int  lane = threadIdx.x;
    const bool bwd  = blockIdx.x >= CRF_B;
    const int  b    = bwd ? (blockIdx.x - CRF_B) : blockIdx.x;
    const int  len  = lengths[b];
    const int  m    = (len + 1) >> 1;       // fwd rows [0,m), bwd rows [m,len)

    {   // tags for this batch
        const int4* tg4 = (const int4*)(tags + (size_t)b * CRF_L);
        int4* tb4 = (int4*)tbuf;
#pragma unroll
        for (int i = 0; i < 4; i++)
            tb4[lane + 32 * i] = __ldg(&tg4[lane + 32 * i]);
    }

    // exp(transition), 16 f32x2 pairs per lane.
    // fwd: pairs over i of column `lane`.  bwd: pairs over j of row `lane`.
    unsigned long long Mp[16];
#pragma unroll
    for (int q = 0; q < 16; q++) {
        float m0, m1;
        if (!bwd) {
            m0 = __expf(__ldg(&trans[(2 * q + 0) * CRF_T + lane]));
            m1 = __expf(__ldg(&trans[(2 * q + 1) * CRF_T + lane]));
        } else {
            m0 = __expf(__ldg(&trans[lane * CRF_T + 2 * q + 0]));
            m1 = __expf(__ldg(&trans[lane * CRF_T + 2 * q + 1]));
        }
        asm("mov.b64 %0, {%1, %2};" : "=l"(Mp[q]) : "f"(m0), "f"(m1));
    }

    const float* erow = emit + (size_t)b * CRF_L * CRF_T;
    const unsigned pb0 = smem_u32(&pbuf[0][0]);
    const unsigned pb1 = smem_u32(&pbuf[1][0]);

    float Ml2 = 0.f;
    float gs  = 0.f;

    auto stage = [&](int c, bool ok) {
        if (ok) {
            const char* src = (const char*)(erow + c * (CHUNK * CRF_T));
            unsigned dst = smem_u32(&ebuf[c & 1][0]);
            asm volatile("cp.async.cg.shared.global [%0], [%1], 16;\n"
                         :: "r"(dst + lane * 16), "l"(src + lane * 16));
            asm volatile("cp.async.cg.shared.global [%0], [%1], 16;\n"
                         :: "r"(dst + 512 + lane * 16), "l"(src + 512 + lane * 16));
        }
        asm volatile("cp.async.commit_group;\n");
    };

    // matvec over the 32-vector published at smem[pin]; g gets element 0.
    auto matvec = [&](unsigned pin, float& g) -> float {
        unsigned long long A0 = 0ull, A1 = 0ull, A2 = 0ull, A3 = 0ull, x, y;
        asm volatile("ld.shared.v2.u64 {%0, %1}, [%2];" : "=l"(x), "=l"(y) : "r"(pin));
        { float hi; asm("mov.b64 {%0, %1}, %2;" : "=f"(g), "=f"(hi) : "l"(x)); }
        asm("fma.rn.f32x2 %0, %1, %2, %0;" : "+l"(A0) : "l"(x), "l"(Mp[0]));
        asm("fma.rn.f32x2 %0, %1, %2, %0;" : "+l"(A1) : "l"(y), "l"(Mp[1]));
#pragma unroll
        for (int q = 1; q < 8; q++) {
            asm volatile("ld.shared.v2.u64 {%0, %1}, [%2];"
                         : "=l"(x), "=l"(y) : "r"(pin + q * 16));
            if (q & 1) {
                asm("fma.rn.f32x2 %0, %1, %2, %0;" : "+l"(A2) : "l"(x), "l"(Mp[2 * q + 0]));
                asm("fma.rn.f32x2 %0, %1, %2, %0;" : "+l"(A3) : "l"(y), "l"(Mp[2 * q + 1]));
            } else {
                asm("fma.rn.f32x2 %0, %1, %2, %0;" : "+l"(A0) : "l"(x), "l"(Mp[2 * q + 0]));
                asm("fma.rn.f32x2 %0, %1, %2, %0;" : "+l"(A1) : "l"(y), "l"(Mp[2 * q + 1]));
            }
        }
        asm("add.rn.f32x2 %0, %0, %1;" : "+l"(A0) : "l"(A1));
        asm("add.rn.f32x2 %0, %0, %1;" : "+l"(A2) : "l"(A3));
        asm("add.rn.f32x2 %0, %0, %1;" : "+l"(A0) : "l"(A2));
        float s0, s1;
        asm("mov.b64 {%0, %1}, %2;" : "=f"(s0), "=f"(s1) : "l"(A0));
        return s0 + s1;
    };

    __syncthreads();   // tbuf visible

    if (!bwd) {
        // ---------------- FORWARD: rows [0, m) ----------------
        const int nch = (m + CHUNK - 1) / CHUNK;
        stage(0, 0 < nch);
        stage(1, 1 < nch);
        float a = 0.f;

        for (int c = 0; c < nch; c++) {
            asm volatile("cp.async.wait_group 1;\n" ::: "memory");
            __syncthreads();
            const float* E = &ebuf[c & 1][0];

            float w[CHUNK];
#pragma unroll
            for (int k = 0; k < CHUNK; k++) w[k] = __expf(E[k * CRF_T + lane]);

            {   // gold partials, rows [0, m)
                const int r = c * CHUNK + lane;
                if (lane < CHUNK && r < m) {
                    const int tg = tbuf[r];
                    gs += E[lane * CRF_T + tg];
                    if (r >= 1) gs += __ldg(&trans[tbuf[r - 1] * CRF_T + tg]);
                }
            }
            stage(c + 2, c + 2 < nch);

#pragma unroll
            for (int k = 0; k < CHUNK; k++) {
                const int row = c * CHUNK + k;
                if (row == 0) {
                    a = w[0];
                    pbuf[0][lane] = a;
                    __syncthreads();
                } else if (row < m) {
                    const unsigned pin  = ((row - 1) & 1) ? pb1 : pb0;
                    const unsigned pout = (row & 1)       ? pb1 : pb0;
                    float g;
                    float s = matvec(pin, g);
                    if ((k & 1) == 0) {      // renorm every 2nd step
                        float rg; asm("rcp.approx.f32 %0, %1;" : "=f"(rg) : "f"(g));
                        Ml2 += __log2f(g);
                        a = s * (w[k] * rg);
                    } else {
                        a = s * w[k];
                    }
                    asm volatile("st.shared.f32 [%0], %1;" :: "r"(pout + lane * 4), "f"(a));
                    __syncthreads();
                }
            }
        }
        // final renorm by lane-0 value (bounds cross-half products)
        float a0 = __shfl_sync(FULL, a, 0);
        { float rg; asm("rcp.approx.f32 %0, %1;" : "=f"(rg) : "f"(a0)); a *= rg; }
        Ml2 += __log2f(a0);
        g_aF[b * CRF_T + lane] = a;
#pragma unroll
        for (int off = 16; off; off >>= 1) gs += __shfl_xor_sync(FULL, gs, off);
        if (lane == 0) g_sF[b] = make_float2(Ml2, gs);
    } else {
        // ---------------- BACKWARD: rows [m, len), high to low ----------------
        const int cL = (len - 1) >> 3;
        const int c0 = m >> 3;
        stage(cL, true);
        stage(cL - 1, cL - 1 >= c0);
        float bta = 1.f;                     // beta_{len-1} = 1

        for (int c = cL; c >= c0; c--) {
            asm volatile("cp.async.wait_group 1;\n" ::: "memory");
            __syncthreads();
            const float* E = &ebuf[c & 1][0];

            float w[CHUNK];
#pragma unroll
            for (int k = 0; k < CHUNK; k++) w[k] = __expf(E[k * CRF_T + lane]);

            {   // gold partials, rows [m, len); r>=m>=1 so transition always
                const int r = c * CHUNK + lane;
                if (lane < CHUNK && r >= m && r < len) {
                    const int tg = tbuf[r];
                    gs += E[lane * CRF_T + tg];
                    gs += __ldg(&trans[tbuf[r - 1] * CRF_T + tg]);
                }
            }
            stage(c - 2, c - 2 >= c0);

#pragma unroll
            for (int k = CHUNK - 1; k >= 0; k--) {
                const int row = c * CHUNK + k;
                if (row >= m && row < len) {
                    const float q = w[k] * bta;
                    const unsigned pout = (row & 1) ? pb1 : pb0;
                    asm volatile("st.shared.f32 [%0], %1;" :: "r"(pout + lane * 4), "f"(q));
                    __syncthreads();
                    float g;
                    float s = matvec(pout, g);
                    if ((k & 1) == 0) {      // renorm every 2nd step
                        float rg; asm("rcp.approx.f32 %0, %1;" : "=f"(rg) : "f"(g));
                        Ml2 += __log2f(g);
                        bta = s * rg;
                    } else {
                        bta = s;
                    }
                }
            }
        }
        // final renorm by lane-0 value
        float b0 = __shfl_sync(FULL, bta, 0);
        { float rg; asm("rcp.approx.f32 %0, %1;" : "=f"(rg) : "f"(b0)); bta *= rg; }
        Ml2 += __log2f(b0);
        g_bB[b * CRF_T + lane] = bta;
#pragma unroll
        for (int off = 16; off; off >>= 1) gs += __shfl_xor_sync(FULL, gs, off);
        if (lane == 0) g_sB[b] = make_float2(Ml2, gs);
    }
}

__global__ __launch_bounds__(256)
void crf_combine_kernel(float* __restrict__ out)
{
    const unsigned FULL = 0xffffffffu;
    const int lane = threadIdx.x & 31;
    const int b = (blockIdx.x * blockDim.x + threadIdx.x) >> 5;
    if (b >= CRF_B) return;

    float prod = g_aF[b * CRF_T + lane] * g_bB[b * CRF_T + lane];
#pragma unroll
    for (int off = 16; off; off >>= 1)
        prod += __shfl_xor_sync(FULL, prod, off);

    if (lane == 0) {
        const float2 sF = g_sF[b];
        const float2 sB = g_sB[b];
        const float logz = (sF.x + sB.x) * 0.6931471805599453f + __logf(prod);
        out[b] = logz - (sF.y + sB.y);
    }
}

extern "C" void kernel_launch(void* const* d_in, const int* in_sizes, int n_in,
                              void* d_out, int out_size)
{
    const float* emit    = (const float*)d_in[0];
    const float* trans   = (const float*)d_in[1];
    const int*   tags    = (const int*)d_in[2];
    const int*   lengths = (const int*)d_in[3];
    float*       out     = (float*)d_out;

    (void)in_sizes; (void)n_in; (void)out_size;

    crf_halves_kernel<<<2 * CRF_B, 32>>>(emit, trans, tags, lengths);
    crf_combine_kernel<<<CRF_B * 32 / 256, 256>>>(out);
}

// round 15
// speedup vs baseline: 1.6057x; 1.0061x over previous
#include <cuda_runtime.h>
#include <cuda_bf16.h>
#include <cstdint>

// CRF loss: out[b] = logZ(b) - gold_score(b).  B=2048, L=512, T=32.
// Forward/backward split: logZ = log sum_i aF_m[i] * bB_m[i], m = ceil(len/2).
// Block bid<2048: forward alpha over rows [0,m).  bid>=2048: backward beta over
// rows [m,len).  32-lane scaled-prob matvec chain (~len/2 steps), renorm every
// 2nd step (fp32-safe; validated rel_err ~1.6e-7).  Separate tiny combine
// kernel (NO device-scope fences in the halves kernel: a gpu-scope fence
// emits CCTL.IVALL on Blackwell and thrashes L1 for co-resident blocks —
// measured +45us in R13).

#define CRF_B 2048
#define CRF_L 512
#define CRF_T 32
#define CHUNK 8

__device__ float  g_aF[CRF_B * CRF_T];
__device__ float  g_bB[CRF_B * CRF_T];
__device__ float2 g_sF[CRF_B];   // {Ml2_fwd, gold_fwd}
__device__ float2 g_sB[CRF_B];   // {Ml2_bwd, gold_bwd}

__device__ __forceinline__ unsigned smem_u32(const void* p) {
    return (unsigned)__cvta_generic_to_shared(p);
}

__global__ __launch_bounds__(32)
void crf_halves_kernel(const float* __restrict__ emit,      // (B, L, T)
                       const float* __restrict__ trans,     // (T, T)
                       const int*   __restrict__ tags,      // (B, L)
                       const int*   __restrict__ lengths)   // (B,)
{
    const unsigned FULL = 0xffffffffu;
    __shared__ __align__(16) float ebuf[2][CHUNK * CRF_T];
    __shared__ __align__(16) float pbuf[2][CRF_T];
    __shared__ __align__(16) int   tbuf[CRF_L];

    const int  lane = threadIdx.x;
    const bool bwd  = blockIdx.x >= CRF_B;
    const int  b    = bwd ? (blockIdx.x - CRF_B) : blockIdx.x;
    const int  len  = lengths[b];
    const int  m    = (len + 1) >> 1;       // fwd rows [0,m), bwd rows [m,len)

    {   // tags for this batch
        const int4* tg4 = (const int4*)(tags + (size_t)b * CRF_L);
        int4* tb4 = (int4*)tbuf;
#pragma unroll
        for (int i = 0; i < 4; i++)
            tb4[lane + 32 * i] = __ldg(&tg4[lane + 32 * i]);
    }

    // exp(transition), 16 f32x2 pairs per lane.
    // fwd: pairs over i of column `lane`.  bwd: pairs over j of row `lane`.
    unsigned long long Mp[16];
#pragma unroll
    for (int q = 0; q < 16; q++) {
        float m0, m1;
        if (!bwd) {
            m0 = __expf(__ldg(&trans[(2 * q + 0) * CRF_T + lane]));
            m1 = __expf(__ldg(&trans[(2 * q + 1) * CRF_T + lane]));
        } else {
            m0 = __expf(__ldg(&trans[lane * CRF_T + 2 * q + 0]));
            m1 = __expf(__ldg(&trans[lane * CRF_T + 2 * q + 1]));
        }
        asm("mov.b64 %0, {%1, %2};" : "=l"(Mp[q]) : "f"(m0), "f"(m1));
    }

    const float* erow = emit + (size_t)b * CRF_L * CRF_T;
    const unsigned pb0 = smem_u32(&pbuf[0][0]);
    const unsigned pb1 = smem_u32(&pbuf[1][0]);

    float Ml2 = 0.f;
    float gs  = 0.f;

    auto stage = [&](int c, bool ok) {
        if (ok) {
            const char* src = (const char*)(erow + c * (CHUNK * CRF_T));
            unsigned dst = smem_u32(&ebuf[c & 1][0]);
            asm volatile("cp.async.cg.shared.global [%0], [%1], 16;\n"
                         :: "r"(dst + lane * 16), "l"(src + lane * 16));
            asm volatile("cp.async.cg.shared.global [%0], [%1], 16;\n"
                         :: "r"(dst + 512 + lane * 16), "l"(src + 512 + lane * 16));
        }
        asm volatile("cp.async.commit_group;\n");
    };

    // matvec over the 32-vector published at smem[pin]; g gets element 0.
    auto matvec = [&](unsigned pin, float& g) -> float {
        unsigned long long A0 = 0ull, A1 = 0ull, A2 = 0ull, A3 = 0ull, x, y;
        asm volatile("ld.shared.v2.u64 {%0, %1}, [%2];" : "=l"(x), "=l"(y) : "r"(pin));
        { float hi; asm("mov.b64 {%0, %1}, %2;" : "=f"(g), "=f"(hi) : "l"(x)); }
        asm("fma.rn.f32x2 %0, %1, %2, %0;" : "+l"(A0) : "l"(x), "l"(Mp[0]));
        asm("fma.rn.f32x2 %0, %1, %2, %0;" : "+l"(A1) : "l"(y), "l"(Mp[1]));
#pragma unroll
        for (int q = 1; q < 8; q++) {
            asm volatile("ld.shared.v2.u64 {%0, %1}, [%2];"
                         : "=l"(x), "=l"(y) : "r"(pin + q * 16));
            if (q & 1) {
                asm("fma.rn.f32x2 %0, %1, %2, %0;" : "+l"(A2) : "l"(x), "l"(Mp[2 * q + 0]));
                asm("fma.rn.f32x2 %0, %1, %2, %0;" : "+l"(A3) : "l"(y), "l"(Mp[2 * q + 1]));
            } else {
                asm("fma.rn.f32x2 %0, %1, %2, %0;" : "+l"(A0) : "l"(x), "l"(Mp[2 * q + 0]));
                asm("fma.rn.f32x2 %0, %1, %2, %0;" : "+l"(A1) : "l"(y), "l"(Mp[2 * q + 1]));
            }
        }
        asm("add.rn.f32x2 %0, %0, %1;" : "+l"(A0) : "l"(A1));
        asm("add.rn.f32x2 %0, %0, %1;" : "+l"(A2) : "l"(A3));
        asm("add.rn.f32x2 %0, %0, %1;" : "+l"(A0) : "l"(A2));
        float s0, s1;
        asm("mov.b64 {%0, %1}, %2;" : "=f"(s0), "=f"(s1) : "l"(A0));
        return s0 + s1;
    };

    __syncthreads();   // tbuf visible

    if (!bwd) {
        // ---------------- FORWARD: rows [0, m) ----------------
        const int nch = (m + CHUNK - 1) / CHUNK;
        stage(0, 0 < nch);
        stage(1, 1 < nch);
        float a = 0.f;

        for (int c = 0; c < nch; c++) {
            asm volatile("cp.async.wait_group 1;\n" ::: "memory");
            __syncthreads();
            const float* E = &ebuf[c & 1][0];

            float w[CHUNK];
#pragma unroll
            for (int k = 0; k < CHUNK; k++) w[k] = __expf(E[k * CRF_T + lane]);

            {   // gold partials, rows [0, m)
                const int r = c * CHUNK + lane;
                if (lane < CHUNK && r < m) {
                    const int tg = tbuf[r];
                    gs += E[lane * CRF_T + tg];
                    if (r >= 1) gs += __ldg(&trans[tbuf[r - 1] * CRF_T + tg]);
                }
            }
            stage(c + 2, c + 2 < nch);

#pragma unroll
            for (int k = 0; k < CHUNK; k++) {
                const int row = c * CHUNK + k;
                if (row == 0) {
                    a = w[0];
                    pbuf[0][lane] = a;
                    __syncthreads();
                } else if (row < m) {
                    const unsigned pin  = ((row - 1) & 1) ? pb1 : pb0;
                    const unsigned pout = (row & 1)       ? pb1 : pb0;
                    float g;
                    float s = matvec(pin, g);
                    if ((k & 1) == 0) {      // renorm every 2nd step
                        float rg; asm("rcp.approx.f32 %0, %1;" : "=f"(rg) : "f"(g));
                        Ml2 += __log2f(g);
                        a = s * (w[k] * rg);
                    } else {
                        a = s * w[k];
                    }
                    asm volatile("st.shared.f32 [%0], %1;" :: "r"(pout + lane * 4), "f"(a));
                    __syncthreads();
                }
            }
        }
        // final renorm by lane-0 value (bounds cross-half products)
        float a0 = __shfl_sync(FULL, a, 0);
        { float rg; asm("rcp.approx.f32 %0, %1;" : "=f"(rg) : "f"(a0)); a *= rg; }
        Ml2 += __log2f(a0);
        g_aF[b * CRF_T + lane] = a;
#pragma unroll
        for (int off = 16; off; off >>= 1) gs += __shfl_xor_sync(FULL, gs, off);
        if (lane == 0) g_sF[b] = make_float2(Ml2, gs);
    } else {
        // ---------------- BACKWARD: rows [m, len), high to low ----------------
        const int cL = (len - 1) >> 3;
        const int c0 = m >> 3;
        stage(cL, true);
        stage(cL - 1, cL - 1 >= c0);
        float bta = 1.f;                     // beta_{len-1} = 1

        for (int c = cL; c >= c0; c--) {
            asm volatile("cp.async.wait_group 1;\n" ::: "memory");
            __syncthreads();
            const float* E = &ebuf[c & 1][0];

            float w[CHUNK];
#pragma unroll
            for (int k = 0; k < CHUNK; k++) w[k] = __expf(E[k * CRF_T + lane]);

            {   // gold partials, rows [m, len); r>=m>=1 so transition always
                const int r = c * CHUNK + lane;
                if (lane < CHUNK && r >= m && r < len) {
                    const int tg = tbuf[r];
                    gs += E[lane * CRF_T + tg];
                    gs += __ldg(&trans[tbuf[r - 1] * CRF_T + tg]);
                }
            }
            stage(c - 2, c - 2 >= c0);

#pragma unroll
            for (int k = CHUNK - 1; k >= 0; k--) {
                const int row = c * CHUNK + k;
                if (row >= m && row < len) {
                    const float q = w[k] * bta;
                    const unsigned pout = (row & 1) ? pb1 : pb0;
                    asm volatile("st.shared.f32 [%0], %1;" :: "r"(pout + lane * 4), "f"(q));
                    __syncthreads();
                    float g;
                    float s = matvec(pout, g);
                    if ((k & 1) == 0) {      // renorm every 2nd step
                        float rg; asm("rcp.approx.f32 %0, %1;" : "=f"(rg) : "f"(g));
                        Ml2 += __log2f(g);
                        bta = s * rg;
                    } else {
                        bta = s;
                    }
                }
            }
        }
        // final renorm by lane-0 value
        float b0 = __shfl_sync(FULL, bta, 0);
        { float rg; asm("rcp.approx.f32 %0, %1;" : "=f"(rg) : "f"(b0)); bta *= rg; }
        Ml2 += __log2f(b0);
        g_bB[b * CRF_T + lane] = bta;
#pragma unroll
        for (int off = 16; off; off >>= 1) gs += __shfl_xor_sync(FULL, gs, off);
        if (lane == 0) g_sB[b] = make_float2(Ml2, gs);
    }
}

__global__ __launch_bounds__(256)
void crf_combine_kernel(float* __restrict__ out)
{
    const unsigned FULL = 0xffffffffu;
    const int lane = threadIdx.x & 31;
    const int b = (blockIdx.x * blockDim.x + threadIdx.x) >> 5;
    if (b >= CRF_B) return;

    float prod = g_aF[b * CRF_T + lane] * g_bB[b * CRF_T + lane];
#pragma unroll
    for (int off = 16; off; off >>= 1)
        prod += __shfl_xor_sync(FULL, prod, off);

    if (lane == 0) {
        const float2 sF = g_sF[b];
        const float2 sB = g_sB[b];
        const float logz = (sF.x + sB.x) * 0.6931471805599453f + __logf(prod);
        out[b] = logz - (sF.y + sB.y);
    }
}

extern "C" void kernel_launch(void* const* d_in, const int* in_sizes, int n_in,
                              void* d_out, int out_size)
{
    const float* emit    = (const float*)d_in[0];
    const float* trans   = (const float*)d_in[1];
    const int*   tags    = (const int*)d_in[2];
    const int*   lengths = (const int*)d_in[3];
    float*       out     = (float*)d_out;

    (void)in_sizes; (void)n_in; (void)out_size;

    crf_halves_kernel<<<2 * CRF_B, 32>>>(emit, trans, tags, lengths);
    crf_combine_kernel<<<CRF_B * 32 / 256, 256>>>(out);
}